// round 3
// baseline (speedup 1.0000x reference)
#include <cuda_runtime.h>
#include <math.h>

#define BB   2
#define SSL  1024
#define NTOK 2048
#define DD   512
#define HHN  8
#define DHH  64
#define HHI  4
#define DII  64
#define FFD  2048
#define EE   8
#define VV   32000
#define KTOP 256
#define NEGV (-1e9f)
#define EPSV 1e-5f
#define LLN  2
#define SCALE 0.125f  /* 1/sqrt(64) */

// ---------------- scratch (static device globals; allocation-free) ----------------
__device__ float g_x  [NTOK*DD];
__device__ float g_h  [NTOK*DD];
__device__ float g_m  [NTOK*DD];
__device__ float g_q  [NTOK*DD];
__device__ float g_k  [NTOK*DD];
__device__ float g_v  [NTOK*DD];
__device__ float g_ao [NTOK*DD];
__device__ float g_moe[NTOK*DD];
__device__ float g_qi [NTOK*HHI*DII];
__device__ float g_ki [NTOK*HHI*DII];
__device__ float g_mask[(size_t)BB*SSL*SSL];
__device__ float g_probs[NTOK*EE];
__device__ int   g_ecount[EE];
__device__ int   g_elist[EE*NTOK];
__device__ float g_egate[EE*NTOK];
__device__ float g_h1[(size_t)EE*NTOK*FFD];   // 128 MB worst-case expert activations

// ---------------- small helpers ----------------
__device__ __forceinline__ float gelu_tanh(float x){
    float x3 = x*x*x;
    return 0.5f*x*(1.f + tanhf(0.7978845608028654f*(x + 0.044715f*x3)));
}

__global__ void k_zerof(float* p, int n){
    int i = blockIdx.x*blockDim.x + threadIdx.x;
    if(i<n) p[i]=0.f;
}
__global__ void k_zeroi(int* p, int n){
    int i = threadIdx.x;
    if(i<n) p[i]=0;
}
__global__ void k_add(float* x, const float* y, int n){
    int i = blockIdx.x*blockDim.x + threadIdx.x;
    if(i<n) x[i]+=y[i];
}

// ---------------- embedding ----------------
__global__ void k_embed(const int* __restrict__ ids,
                        const float* __restrict__ tok,
                        const float* __restrict__ pos){
    int n = blockIdx.x; int t = threadIdx.x;     // blockDim = 512
    int id = ids[n];
    int s  = n % SSL;
    g_x[(size_t)n*DD + t] = tok[(size_t)id*DD + t] + pos[(size_t)s*DD + t];
}

// ---------------- layernorm (D = 512, block 256) ----------------
__global__ __launch_bounds__(256) void k_ln(const float* __restrict__ in,
                                            const float* __restrict__ g,
                                            const float* __restrict__ b,
                                            float* __restrict__ out){
    int r = blockIdx.x; int t = threadIdx.x;
    __shared__ float red[256];
    float v0 = in[(size_t)r*DD + t];
    float v1 = in[(size_t)r*DD + t + 256];
    red[t] = v0 + v1;
    __syncthreads();
    for(int s=128;s>0;s>>=1){ if(t<s) red[t]+=red[t+s]; __syncthreads(); }
    float mu = red[0] * (1.0f/DD);
    __syncthreads();
    float d0 = v0-mu, d1 = v1-mu;
    red[t] = d0*d0 + d1*d1;
    __syncthreads();
    for(int s=128;s>0;s>>=1){ if(t<s) red[t]+=red[t+s]; __syncthreads(); }
    float rs = rsqrtf(red[0]*(1.0f/DD) + EPSV);
    out[(size_t)r*DD + t]       = d0*rs*g[t]     + b[t];
    out[(size_t)r*DD + t + 256] = d1*rs*g[t+256] + b[t+256];
}

// ---------------- generic SGEMM: C = A[MxK] @ B[KxN] (+bias) (+res) ----------------
__global__ __launch_bounds__(256) void k_sgemm(const float* __restrict__ A,
                                               const float* __restrict__ Bm,
                                               const float* __restrict__ bias,
                                               const float* __restrict__ res,
                                               float* __restrict__ C,
                                               int M, int N, int Kd){
    __shared__ float As[16][64];
    __shared__ float Bs[16][64];
    int tx = threadIdx.x & 15, ty = threadIdx.x >> 4;
    int row0 = blockIdx.y*64, col0 = blockIdx.x*64;
    float acc[4][4] = {};
    for(int k0=0;k0<Kd;k0+=16){
        #pragma unroll
        for(int i=threadIdx.x;i<1024;i+=256){
            int m=i>>4, kk=i&15; int r=row0+m;
            As[kk][m] = (r<M)? A[(size_t)r*Kd + k0+kk] : 0.f;
        }
        #pragma unroll
        for(int i=threadIdx.x;i<1024;i+=256){
            int kk=i>>6, c=i&63; int cc=col0+c;
            Bs[kk][c] = (cc<N)? Bm[(size_t)(k0+kk)*N + cc] : 0.f;
        }
        __syncthreads();
        #pragma unroll
        for(int kk=0;kk<16;kk++){
            float4 a4 = *(const float4*)&As[kk][ty*4];
            float4 b4 = *(const float4*)&Bs[kk][tx*4];
            float a[4]={a4.x,a4.y,a4.z,a4.w};
            float b[4]={b4.x,b4.y,b4.z,b4.w};
            #pragma unroll
            for(int i=0;i<4;i++)
                #pragma unroll
                for(int j=0;j<4;j++)
                    acc[i][j] += a[i]*b[j];
        }
        __syncthreads();
    }
    #pragma unroll
    for(int i=0;i<4;i++){
        int r=row0+ty*4+i; if(r>=M) continue;
        #pragma unroll
        for(int j=0;j<4;j++){
            int c=col0+tx*4+j; if(c>=N) continue;
            float v = acc[i][j];
            if(bias) v += bias[c];
            if(res)  v += res[(size_t)r*N + c];
            C[(size_t)r*N + c] = v;
        }
    }
}

// ---------------- lightning indexer scores: vals = sum_h relu(qi_h . ki_h)*hw[h] + causal ----------------
// grid (S/64, S/64, B), block 256
__global__ __launch_bounds__(256) void k_idxscore(const float* __restrict__ hw){
    int kt=blockIdx.x, qt=blockIdx.y, b=blockIdx.z;
    int tx=threadIdx.x&15, ty=threadIdx.x>>4;
    __shared__ float Qs[64][65];
    __shared__ float Ks[64][65];
    float acc[4][4] = {};
    for(int h=0;h<HHI;h++){
        for(int i=threadIdx.x;i<4096;i+=256){
            int r=i>>6, d=i&63;
            Qs[r][d] = g_qi[(size_t)(b*SSL + qt*64 + r)*(HHI*DII) + h*64 + d];
            Ks[r][d] = g_ki[(size_t)(b*SSL + kt*64 + r)*(HHI*DII) + h*64 + d];
        }
        __syncthreads();
        float w = hw[h];
        float dot[4][4] = {};
        #pragma unroll 16
        for(int d=0;d<64;d++){
            float a[4], bb[4];
            #pragma unroll
            for(int i=0;i<4;i++) a[i]=Qs[ty*4+i][d];
            #pragma unroll
            for(int j=0;j<4;j++) bb[j]=Ks[tx*4+j][d];
            #pragma unroll
            for(int i=0;i<4;i++)
                #pragma unroll
                for(int j=0;j<4;j++)
                    dot[i][j]+=a[i]*bb[j];
        }
        #pragma unroll
        for(int i=0;i<4;i++)
            #pragma unroll
            for(int j=0;j<4;j++)
                acc[i][j] += fmaxf(dot[i][j],0.f)*w;
        __syncthreads();
    }
    #pragma unroll
    for(int i=0;i<4;i++){
        int q = qt*64 + ty*4 + i;
        #pragma unroll
        for(int j=0;j<4;j++){
            int k = kt*64 + tx*4 + j;
            g_mask[((size_t)b*SSL + q)*SSL + k] = acc[i][j] + ((k<=q)?0.f:NEGV);
        }
    }
}

// ---------------- exact top-K threshold + final additive mask ----------------
// grid (S, B), block 512; bitonic sort 1024 descending, thr = [K-1]
__global__ __launch_bounds__(512) void k_topk(){
    int q=blockIdx.x, b=blockIdx.y, t=threadIdx.x;
    __shared__ float s[1024];
    size_t base = ((size_t)b*SSL + q)*SSL;
    s[t]     = g_mask[base+t];
    s[t+512] = g_mask[base+t+512];
    __syncthreads();
    for(int size=2;size<=1024;size<<=1){
        for(int stride=size>>1;stride>0;stride>>=1){
            int lo = 2*stride*(t/stride) + (t%stride);
            int hi = lo + stride;
            bool desc = ((lo & size)==0);
            float a=s[lo], bv=s[hi];
            if((a<bv)==desc){ s[lo]=bv; s[hi]=a; }
            __syncthreads();
        }
    }
    float thr = s[KTOP-1];
    for(int k=t;k<SSL;k+=512){
        float v = g_mask[base+k];
        g_mask[base+k] = (k<=q && v>=thr)? 0.f : NEGV;
    }
}

// ---------------- flash-style attention: 16 queries/block, online softmax ----------------
// grid (S/16, H, B), block 256
__global__ __launch_bounds__(256) void k_attn(){
    int qt=blockIdx.x, h=blockIdx.y, b=blockIdx.z;
    int t=threadIdx.x;
    int ql = t & 15;
    int dg = t >> 4;       // 0..15; d-range dg*4 .. dg*4+3
    __shared__ float qs[16][65];
    __shared__ float Ks[64][65];
    __shared__ float Vs[64][65];
    __shared__ float Sc[16][65];
    __shared__ float mrow[16], lrow[16], crow[16];
    int q0 = qt*16;
    for(int i=t;i<16*64;i+=256){
        int r=i>>6, d=i&63;
        qs[r][d] = g_q[(size_t)(b*SSL + q0 + r)*DD + h*64 + d];
    }
    if(t<16){ mrow[t]=-1e30f; lrow[t]=0.f; }
    float oacc[4] = {0.f,0.f,0.f,0.f};
    __syncthreads();
    for(int k0=0;k0<SSL;k0+=64){
        for(int i=t;i<4096;i+=256){
            int r=i>>6, d=i&63;
            Ks[r][d] = g_k[(size_t)(b*SSL + k0 + r)*DD + h*64 + d];
            Vs[r][d] = g_v[(size_t)(b*SSL + k0 + r)*DD + h*64 + d];
        }
        __syncthreads();
        #pragma unroll
        for(int j=0;j<4;j++){
            int kc = dg*4 + j;
            float acc=0.f;
            #pragma unroll 16
            for(int d=0;d<64;d++) acc += qs[ql][d]*Ks[kc][d];
            Sc[ql][kc] = acc*SCALE + g_mask[((size_t)b*SSL + (q0+ql))*SSL + k0 + kc];
        }
        __syncthreads();
        if(t<16){
            float mold = mrow[t];
            float tmax = mold;
            for(int k=0;k<64;k++) tmax = fmaxf(tmax, Sc[t][k]);
            float c = __expf(mold - tmax);
            float ls = lrow[t]*c;
            for(int k=0;k<64;k++){ float p=__expf(Sc[t][k]-tmax); Sc[t][k]=p; ls+=p; }
            mrow[t]=tmax; lrow[t]=ls; crow[t]=c;
        }
        __syncthreads();
        float c = crow[ql];
        #pragma unroll
        for(int j=0;j<4;j++){
            int d = dg*4 + j;
            float a = oacc[j]*c;
            #pragma unroll 16
            for(int k=0;k<64;k++) a += Sc[ql][k]*Vs[k][d];
            oacc[j]=a;
        }
        __syncthreads();
    }
    float linv = 1.0f/lrow[ql];
    #pragma unroll
    for(int j=0;j<4;j++){
        int d = dg*4 + j;
        g_ao[(size_t)(b*SSL + q0 + ql)*DD + h*64 + d] = oacc[j]*linv;
    }
}

// ---------------- router softmax + top-2 gating + expert bucketing ----------------
__global__ void k_gate(){
    int n = blockIdx.x*blockDim.x + threadIdx.x;
    if(n>=NTOK) return;
    float p[EE]; float mx=-1e30f;
    for(int e=0;e<EE;e++){ p[e]=g_probs[n*EE+e]; mx=fmaxf(mx,p[e]); }
    for(int e=0;e<EE;e++) p[e]=__expf(p[e]-mx);
    int e1=0;
    for(int e=1;e<EE;e++) if(p[e]>p[e1]) e1=e;
    int e2=-1;
    for(int e=0;e<EE;e++) if(e!=e1 && (e2<0 || p[e]>p[e2])) e2=e;
    float den = p[e1]+p[e2];
    float w1 = p[e1]/den, w2 = p[e2]/den;
    int pos = atomicAdd(&g_ecount[e1],1);
    g_elist[e1*NTOK+pos]=n; g_egate[e1*NTOK+pos]=w1;
    pos = atomicAdd(&g_ecount[e2],1);
    g_elist[e2*NTOK+pos]=n; g_egate[e2*NTOK+pos]=w2;
}

// ---------------- MoE GEMM1 (gathered rows) with GELU: h1 = gelu(m[t] @ W1[e] + b1[e]) ----------------
// grid (F/64, NTOK/64, E)
__global__ __launch_bounds__(256) void k_moe_g1(const float* __restrict__ W1,
                                                const float* __restrict__ B1){
    int e = blockIdx.z;
    int cnt = g_ecount[e];
    int row0 = blockIdx.y*64;
    if(row0 >= cnt) return;
    int col0 = blockIdx.x*64;
    const float* W   = W1 + (size_t)e*DD*FFD;
    const float* bia = B1 + (size_t)e*FFD;
    __shared__ float As[16][64];
    __shared__ float Bs[16][64];
    __shared__ int trow[64];
    int tx=threadIdx.x&15, ty=threadIdx.x>>4;
    if(threadIdx.x<64){
        int r = row0 + threadIdx.x;
        trow[threadIdx.x] = (r<cnt)? g_elist[e*NTOK + r] : -1;
    }
    __syncthreads();
    float acc[4][4] = {};
    for(int k0=0;k0<DD;k0+=16){
        #pragma unroll
        for(int i=threadIdx.x;i<1024;i+=256){
            int m=i>>4, kk=i&15; int tk=trow[m];
            As[kk][m] = (tk>=0)? g_m[(size_t)tk*DD + k0+kk] : 0.f;
        }
        #pragma unroll
        for(int i=threadIdx.x;i<1024;i+=256){
            int kk=i>>6, c=i&63;
            Bs[kk][c] = W[(size_t)(k0+kk)*FFD + col0+c];
        }
        __syncthreads();
        #pragma unroll
        for(int kk=0;kk<16;kk++){
            float4 a4 = *(const float4*)&As[kk][ty*4];
            float4 b4 = *(const float4*)&Bs[kk][tx*4];
            float a[4]={a4.x,a4.y,a4.z,a4.w};
            float b[4]={b4.x,b4.y,b4.z,b4.w};
            #pragma unroll
            for(int i=0;i<4;i++)
                #pragma unroll
                for(int j=0;j<4;j++)
                    acc[i][j]+=a[i]*b[j];
        }
        __syncthreads();
    }
    #pragma unroll
    for(int i=0;i<4;i++){
        int r=row0+ty*4+i; if(r>=cnt) continue;
        #pragma unroll
        for(int j=0;j<4;j++){
            int c=col0+tx*4+j;
            g_h1[(size_t)e*NTOK*FFD + (size_t)r*FFD + c] = gelu_tanh(acc[i][j]+bia[c]);
        }
    }
}

// ---------------- MoE GEMM2 + gated atomic scatter: moe[t] += gv*(h1 @ W2[e] + b2[e]) ----------------
// grid (D/64, NTOK/64, E)
__global__ __launch_bounds__(256) void k_moe_g2(const float* __restrict__ W2,
                                                const float* __restrict__ B2){
    int e = blockIdx.z;
    int cnt = g_ecount[e];
    int row0 = blockIdx.y*64;
    if(row0 >= cnt) return;
    int col0 = blockIdx.x*64;
    const float* A  = g_h1 + (size_t)e*NTOK*FFD;
    const float* W  = W2 + (size_t)e*FFD*DD;
    const float* b2 = B2 + (size_t)e*DD;
    __shared__ float As[16][64];
    __shared__ float Bs[16][64];
    int tx=threadIdx.x&15, ty=threadIdx.x>>4;
    float acc[4][4] = {};
    for(int k0=0;k0<FFD;k0+=16){
        #pragma unroll
        for(int i=threadIdx.x;i<1024;i+=256){
            int m=i>>4, kk=i&15; int r=row0+m;
            As[kk][m] = (r<cnt)? A[(size_t)r*FFD + k0+kk] : 0.f;
        }
        #pragma unroll
        for(int i=threadIdx.x;i<1024;i+=256){
            int kk=i>>6, c=i&63;
            Bs[kk][c] = W[(size_t)(k0+kk)*DD + col0+c];
        }
        __syncthreads();
        #pragma unroll
        for(int kk=0;kk<16;kk++){
            float4 a4 = *(const float4*)&As[kk][ty*4];
            float4 b4 = *(const float4*)&Bs[kk][tx*4];
            float a[4]={a4.x,a4.y,a4.z,a4.w};
            float b[4]={b4.x,b4.y,b4.z,b4.w};
            #pragma unroll
            for(int i=0;i<4;i++)
                #pragma unroll
                for(int j=0;j<4;j++)
                    acc[i][j]+=a[i]*b[j];
        }
        __syncthreads();
    }
    #pragma unroll
    for(int i=0;i<4;i++){
        int r=row0+ty*4+i; if(r>=cnt) continue;
        int tok = g_elist[e*NTOK + r];
        float gv = g_egate[e*NTOK + r];
        #pragma unroll
        for(int j=0;j<4;j++){
            int c=col0+tx*4+j;
            atomicAdd(&g_moe[(size_t)tok*DD + c], gv*(acc[i][j]+b2[c]));
        }
    }
}

// ================================ host ================================
extern "C" void kernel_launch(void* const* d_in, const int* in_sizes, int n_in,
                              void* d_out, int out_size){
    (void)in_sizes; (void)n_in; (void)out_size;
    const int*   ids  = (const int*)  d_in[0];
    const float* tok  = (const float*)d_in[1];
    const float* pos  = (const float*)d_in[2];
    const float* ln1g = (const float*)d_in[3];
    const float* ln1b = (const float*)d_in[4];
    const float* iqw  = (const float*)d_in[5];
    const float* iqb  = (const float*)d_in[6];
    const float* ikw  = (const float*)d_in[7];
    const float* ikb  = (const float*)d_in[8];
    const float* ihw  = (const float*)d_in[9];
    const float* wq   = (const float*)d_in[10];
    const float* bq   = (const float*)d_in[11];
    const float* wk   = (const float*)d_in[12];
    const float* bk   = (const float*)d_in[13];
    const float* wv   = (const float*)d_in[14];
    const float* bv   = (const float*)d_in[15];
    const float* wo   = (const float*)d_in[16];
    const float* bo   = (const float*)d_in[17];
    const float* ln2g = (const float*)d_in[18];
    const float* ln2b = (const float*)d_in[19];
    const float* rw   = (const float*)d_in[20];
    const float* rb   = (const float*)d_in[21];
    const float* ew1  = (const float*)d_in[22];
    const float* eb1  = (const float*)d_in[23];
    const float* ew2  = (const float*)d_in[24];
    const float* eb2  = (const float*)d_in[25];
    const float* lnfg = (const float*)d_in[26];
    const float* lnfb = (const float*)d_in[27];
    const float* ow   = (const float*)d_in[28];
    const float* ob   = (const float*)d_in[29];
    float* out = (float*)d_out;

    float *px,*ph,*pm,*pq,*pk,*pv,*pao,*pqi,*pki,*pprobs,*pmoe;
    int *pec;
    cudaGetSymbolAddress((void**)&px,  g_x);
    cudaGetSymbolAddress((void**)&ph,  g_h);
    cudaGetSymbolAddress((void**)&pm,  g_m);
    cudaGetSymbolAddress((void**)&pq,  g_q);
    cudaGetSymbolAddress((void**)&pk,  g_k);
    cudaGetSymbolAddress((void**)&pv,  g_v);
    cudaGetSymbolAddress((void**)&pao, g_ao);
    cudaGetSymbolAddress((void**)&pqi, g_qi);
    cudaGetSymbolAddress((void**)&pki, g_ki);
    cudaGetSymbolAddress((void**)&pprobs, g_probs);
    cudaGetSymbolAddress((void**)&pmoe, g_moe);
    cudaGetSymbolAddress((void**)&pec, g_ecount);

    k_embed<<<NTOK,512>>>(ids, tok, pos);

    for(int l=0;l<LLN;l++){
        // --- attention block ---
        k_ln<<<NTOK,256>>>(px, ln1g + l*DD, ln1b + l*DD, ph);
        k_sgemm<<<dim3(4,32),256>>>(ph, iqw + (size_t)l*DD*HHI*DII, iqb + l*HHI*DII, nullptr, pqi, NTOK, HHI*DII, DD);
        k_sgemm<<<dim3(4,32),256>>>(ph, ikw + (size_t)l*DD*HHI*DII, ikb + l*HHI*DII, nullptr, pki, NTOK, HHI*DII, DD);
        k_idxscore<<<dim3(SSL/64, SSL/64, BB),256>>>(ihw + l*HHI);
        k_topk<<<dim3(SSL, BB),512>>>();
        k_sgemm<<<dim3(8,32),256>>>(ph, wq + (size_t)l*DD*DD, bq + l*DD, nullptr, pq, NTOK, DD, DD);
        k_sgemm<<<dim3(8,32),256>>>(ph, wk + (size_t)l*DD*DD, bk + l*DD, nullptr, pk, NTOK, DD, DD);
        k_sgemm<<<dim3(8,32),256>>>(ph, wv + (size_t)l*DD*DD, bv + l*DD, nullptr, pv, NTOK, DD, DD);
        k_attn<<<dim3(SSL/16, HHN, BB),256>>>();
        // x = x + attn_out @ wo + bo   (residual fused into epilogue)
        k_sgemm<<<dim3(8,32),256>>>(pao, wo + (size_t)l*DD*DD, bo + l*DD, px, px, NTOK, DD, DD);

        // --- MoE block ---
        k_ln<<<NTOK,256>>>(px, ln2g + l*DD, ln2b + l*DD, pm);
        k_sgemm<<<dim3(1,32),256>>>(pm, rw + (size_t)l*DD*EE, rb + l*EE, nullptr, pprobs, NTOK, EE, DD);
        k_zeroi<<<1,32>>>(pec, EE);
        k_gate<<<NTOK/256,256>>>();
        k_zerof<<<(NTOK*DD)/256,256>>>(pmoe, NTOK*DD);
        k_moe_g1<<<dim3(FFD/64, NTOK/64, EE),256>>>(ew1 + (size_t)l*EE*DD*FFD, eb1 + (size_t)l*EE*FFD);
        k_moe_g2<<<dim3(DD/64, NTOK/64, EE),256>>>(ew2 + (size_t)l*EE*FFD*DD, eb2 + (size_t)l*EE*DD);
        k_add<<<(NTOK*DD)/256,256>>>(px, pmoe, NTOK*DD);
    }

    // --- final LN + vocab projection ---
    k_ln<<<NTOK,256>>>(px, lnfg, lnfb, ph);
    k_sgemm<<<dim3(VV/64, NTOK/64),256>>>(ph, ow, ob, nullptr, out, NTOK, VV, DD);
}

// round 4
// speedup vs baseline: 1.3082x; 1.3082x over previous
#include <cuda_runtime.h>
#include <math.h>

#define BB   2
#define SSL  1024
#define NTOK 2048
#define DD   512
#define HHN  8
#define DHH  64
#define HHI  4
#define DII  64
#define FFD  2048
#define EE   8
#define VV   32000
#define KTOP 256
#define NEGV (-1e9f)
#define EPSV 1e-5f
#define LLN  2
#define SCALE 0.125f

// ---------------- scratch ----------------
__device__ float g_x  [NTOK*DD];
__device__ float g_h  [NTOK*DD];
__device__ float g_m  [NTOK*DD];
__device__ float g_q  [NTOK*DD];
__device__ float g_k  [NTOK*DD];
__device__ float g_v  [NTOK*DD];
__device__ float g_ao [NTOK*DD];
__device__ float g_moe[NTOK*DD];
__device__ float g_qi [NTOK*HHI*DII];
__device__ float g_ki [NTOK*HHI*DII];
__device__ float g_mask[(size_t)BB*SSL*SSL];
__device__ float g_probs[NTOK*EE];
__device__ int   g_ecount[EE];
__device__ int   g_elist[EE*NTOK];
__device__ float g_egate[EE*NTOK];
__device__ float g_h1[(size_t)EE*NTOK*FFD];

__device__ __forceinline__ float gelu_tanh(float x){
    float x3 = x*x*x;
    return 0.5f*x*(1.f + tanhf(0.7978845608028654f*(x + 0.044715f*x3)));
}

__global__ void k_zerof(float* p, int n){
    int i = blockIdx.x*blockDim.x + threadIdx.x;
    if(i<n) p[i]=0.f;
}
__global__ void k_zeroi(int* p, int n){
    int i = threadIdx.x;
    if(i<n) p[i]=0;
}
__global__ void k_add(float* x, const float* y, int n){
    int i = blockIdx.x*blockDim.x + threadIdx.x;
    if(i<n) x[i]+=y[i];
}

// ---------------- embedding ----------------
__global__ void k_embed(const int* __restrict__ ids,
                        const float* __restrict__ tok,
                        const float* __restrict__ pos){
    int n = blockIdx.x; int t = threadIdx.x;
    int id = ids[n];
    int s  = n % SSL;
    g_x[(size_t)n*DD + t] = tok[(size_t)id*DD + t] + pos[(size_t)s*DD + t];
}

// ---------------- layernorm ----------------
__global__ __launch_bounds__(256) void k_ln(const float* __restrict__ in,
                                            const float* __restrict__ g,
                                            const float* __restrict__ b,
                                            float* __restrict__ out){
    int r = blockIdx.x; int t = threadIdx.x;
    __shared__ float red[256];
    float v0 = in[(size_t)r*DD + t];
    float v1 = in[(size_t)r*DD + t + 256];
    red[t] = v0 + v1;
    __syncthreads();
    for(int s=128;s>0;s>>=1){ if(t<s) red[t]+=red[t+s]; __syncthreads(); }
    float mu = red[0] * (1.0f/DD);
    __syncthreads();
    float d0 = v0-mu, d1 = v1-mu;
    red[t] = d0*d0 + d1*d1;
    __syncthreads();
    for(int s=128;s>0;s>>=1){ if(t<s) red[t]+=red[t+s]; __syncthreads(); }
    float rs = rsqrtf(red[0]*(1.0f/DD) + EPSV);
    out[(size_t)r*DD + t]       = d0*rs*g[t]     + b[t];
    out[(size_t)r*DD + t + 256] = d1*rs*g[t+256] + b[t+256];
}

// ========== high-throughput 128x128 SGEMM core (M%128==0, N%128==0, K%8==0) ==========
// 256 threads, 8x8 microtile, BK=8, double buffered, float4 global + shared.
struct B3 {
    const float *B0, *B1, *B2;
    const float *c0, *c1, *c2;
    float *C0, *C1, *C2;
};

__device__ __forceinline__ void gemm128_body(
    const float* __restrict__ A, const float* __restrict__ B,
    const float* __restrict__ bias, const float* __restrict__ res,
    float* __restrict__ C, int N, int K)
{
    __shared__ float As[2][8][132];
    __shared__ float Bs[2][8][128];
    int tid = threadIdx.x;
    int row0 = blockIdx.y*128, col0 = blockIdx.x*128;
    int arow = tid>>1,  acol = (tid&1)*4;
    int brow = tid>>5,  bcol = (tid&31)*4;
    const float* Aptr = A + (size_t)(row0+arow)*K + acol;
    const float* Bptr = B + (size_t)brow*N + col0 + bcol;

    float4 a4 = *(const float4*)Aptr;
    float4 b4 = *(const float4*)Bptr;
    As[0][acol+0][arow]=a4.x; As[0][acol+1][arow]=a4.y;
    As[0][acol+2][arow]=a4.z; As[0][acol+3][arow]=a4.w;
    *(float4*)&Bs[0][brow][bcol] = b4;
    __syncthreads();

    int tx = tid&15, ty = tid>>4;
    float acc[8][8] = {};
    int buf = 0;
    for(int k0=8;k0<=K;k0+=8){
        if(k0<K){
            a4 = *(const float4*)(Aptr + k0);
            b4 = *(const float4*)(Bptr + (size_t)k0*N);
        }
        #pragma unroll
        for(int kk=0;kk<8;kk++){
            float4 a0 = *(const float4*)&As[buf][kk][ty*8];
            float4 a1 = *(const float4*)&As[buf][kk][ty*8+4];
            float4 b0 = *(const float4*)&Bs[buf][kk][tx*8];
            float4 b1 = *(const float4*)&Bs[buf][kk][tx*8+4];
            float av[8]={a0.x,a0.y,a0.z,a0.w,a1.x,a1.y,a1.z,a1.w};
            float bv[8]={b0.x,b0.y,b0.z,b0.w,b1.x,b1.y,b1.z,b1.w};
            #pragma unroll
            for(int i=0;i<8;i++)
                #pragma unroll
                for(int j=0;j<8;j++)
                    acc[i][j] += av[i]*bv[j];
        }
        if(k0<K){
            buf ^= 1;
            As[buf][acol+0][arow]=a4.x; As[buf][acol+1][arow]=a4.y;
            As[buf][acol+2][arow]=a4.z; As[buf][acol+3][arow]=a4.w;
            *(float4*)&Bs[buf][brow][bcol] = b4;
            __syncthreads();
        }
    }
    #pragma unroll
    for(int i=0;i<8;i++){
        int r = row0 + ty*8 + i;
        #pragma unroll
        for(int j=0;j<8;j+=4){
            int c = col0 + tx*8 + j;
            float4 v = {acc[i][j],acc[i][j+1],acc[i][j+2],acc[i][j+3]};
            if(bias){
                float4 bb = *(const float4*)&bias[c];
                v.x+=bb.x; v.y+=bb.y; v.z+=bb.z; v.w+=bb.w;
            }
            if(res){
                float4 rr = *(const float4*)&res[(size_t)r*N + c];
                v.x+=rr.x; v.y+=rr.y; v.z+=rr.z; v.w+=rr.w;
            }
            *(float4*)&C[(size_t)r*N + c] = v;
        }
    }
}

__global__ __launch_bounds__(256) void k_gemm128(const float* __restrict__ A,
                                                 const float* __restrict__ B,
                                                 const float* __restrict__ bias,
                                                 const float* __restrict__ res,
                                                 float* __restrict__ C,
                                                 int N, int K){
    gemm128_body(A,B,bias,res,C,N,K);
}

__global__ __launch_bounds__(256) void k_gemm128b3(const float* __restrict__ A,
                                                   B3 p, int N, int K){
    const float *B, *bias; float *C;
    if(blockIdx.z==0){ B=p.B0; bias=p.c0; C=p.C0; }
    else if(blockIdx.z==1){ B=p.B1; bias=p.c1; C=p.C1; }
    else { B=p.B2; bias=p.c2; C=p.C2; }
    gemm128_body(A,B,bias,nullptr,C,N,K);
}

// ---------------- MoE GEMM1: gathered rows + GELU epilogue ----------------
// grid (FFD/128, NTOK/128, E)
__global__ __launch_bounds__(256) void k_moe1(const float* __restrict__ W1,
                                              const float* __restrict__ B1){
    int e = blockIdx.z;
    int cnt = g_ecount[e];
    int row0 = blockIdx.y*128;
    if(row0 >= cnt) return;
    int col0 = blockIdx.x*128;
    const float* W   = W1 + (size_t)e*DD*FFD;
    const float* bia = B1 + (size_t)e*FFD;
    __shared__ int trow[128];
    __shared__ float As[2][8][132];
    __shared__ float Bs[2][8][128];
    int tid = threadIdx.x;
    if(tid<128){
        int r = row0 + tid;
        trow[tid] = (r<cnt)? g_elist[e*NTOK + r] : g_elist[e*NTOK];
    }
    __syncthreads();
    int arow = tid>>1, acol = (tid&1)*4;
    int brow = tid>>5, bcol = (tid&31)*4;
    const float* Aptr = g_m + (size_t)trow[arow]*DD + acol;
    const float* Bptr = W + (size_t)brow*FFD + col0 + bcol;

    float4 a4 = *(const float4*)Aptr;
    float4 b4 = *(const float4*)Bptr;
    As[0][acol+0][arow]=a4.x; As[0][acol+1][arow]=a4.y;
    As[0][acol+2][arow]=a4.z; As[0][acol+3][arow]=a4.w;
    *(float4*)&Bs[0][brow][bcol] = b4;
    __syncthreads();

    int tx = tid&15, ty = tid>>4;
    float acc[8][8] = {};
    int buf = 0;
    for(int k0=8;k0<=DD;k0+=8){
        if(k0<DD){
            a4 = *(const float4*)(Aptr + k0);
            b4 = *(const float4*)(Bptr + (size_t)k0*FFD);
        }
        #pragma unroll
        for(int kk=0;kk<8;kk++){
            float4 a0 = *(const float4*)&As[buf][kk][ty*8];
            float4 a1 = *(const float4*)&As[buf][kk][ty*8+4];
            float4 b0 = *(const float4*)&Bs[buf][kk][tx*8];
            float4 b1 = *(const float4*)&Bs[buf][kk][tx*8+4];
            float av[8]={a0.x,a0.y,a0.z,a0.w,a1.x,a1.y,a1.z,a1.w};
            float bv[8]={b0.x,b0.y,b0.z,b0.w,b1.x,b1.y,b1.z,b1.w};
            #pragma unroll
            for(int i=0;i<8;i++)
                #pragma unroll
                for(int j=0;j<8;j++)
                    acc[i][j] += av[i]*bv[j];
        }
        if(k0<DD){
            buf ^= 1;
            As[buf][acol+0][arow]=a4.x; As[buf][acol+1][arow]=a4.y;
            As[buf][acol+2][arow]=a4.z; As[buf][acol+3][arow]=a4.w;
            *(float4*)&Bs[buf][brow][bcol] = b4;
            __syncthreads();
        }
    }
    float* H = g_h1 + (size_t)e*NTOK*FFD;
    #pragma unroll
    for(int i=0;i<8;i++){
        int r = row0 + ty*8 + i;
        if(r>=cnt) continue;
        #pragma unroll
        for(int j=0;j<8;j++){
            int c = col0 + tx*8 + j;
            H[(size_t)r*FFD + c] = gelu_tanh(acc[i][j] + bia[c]);
        }
    }
}

// ---------------- MoE GEMM2: split-K=2, gated atomic scatter ----------------
// grid (DD/128, NTOK/128, E*2)
__global__ __launch_bounds__(256) void k_moe2(const float* __restrict__ W2,
                                              const float* __restrict__ B2){
    int e = blockIdx.z >> 1;
    int s = blockIdx.z & 1;
    int cnt = g_ecount[e];
    int row0 = blockIdx.y*128;
    if(row0 >= cnt) return;
    int col0 = blockIdx.x*128;
    int kbeg = s * (FFD/2);
    const float* A  = g_h1 + (size_t)e*NTOK*FFD;
    const float* W  = W2 + (size_t)e*FFD*DD;
    const float* b2 = B2 + (size_t)e*DD;
    __shared__ float As[2][8][132];
    __shared__ float Bs[2][8][128];
    int tid = threadIdx.x;
    int arow = tid>>1, acol = (tid&1)*4;
    int brow = tid>>5, bcol = (tid&31)*4;
    const float* Aptr = A + (size_t)(row0+arow)*FFD + kbeg + acol;
    const float* Bptr = W + (size_t)(kbeg+brow)*DD + col0 + bcol;

    float4 a4 = *(const float4*)Aptr;
    float4 b4 = *(const float4*)Bptr;
    As[0][acol+0][arow]=a4.x; As[0][acol+1][arow]=a4.y;
    As[0][acol+2][arow]=a4.z; As[0][acol+3][arow]=a4.w;
    *(float4*)&Bs[0][brow][bcol] = b4;
    __syncthreads();

    int tx = tid&15, ty = tid>>4;
    float acc[8][8] = {};
    int buf = 0;
    const int KK = FFD/2;
    for(int k0=8;k0<=KK;k0+=8){
        if(k0<KK){
            a4 = *(const float4*)(Aptr + k0);
            b4 = *(const float4*)(Bptr + (size_t)k0*DD);
        }
        #pragma unroll
        for(int kk=0;kk<8;kk++){
            float4 a0 = *(const float4*)&As[buf][kk][ty*8];
            float4 a1 = *(const float4*)&As[buf][kk][ty*8+4];
            float4 b0 = *(const float4*)&Bs[buf][kk][tx*8];
            float4 b1 = *(const float4*)&Bs[buf][kk][tx*8+4];
            float av[8]={a0.x,a0.y,a0.z,a0.w,a1.x,a1.y,a1.z,a1.w};
            float bv[8]={b0.x,b0.y,b0.z,b0.w,b1.x,b1.y,b1.z,b1.w};
            #pragma unroll
            for(int i=0;i<8;i++)
                #pragma unroll
                for(int j=0;j<8;j++)
                    acc[i][j] += av[i]*bv[j];
        }
        if(k0<KK){
            buf ^= 1;
            As[buf][acol+0][arow]=a4.x; As[buf][acol+1][arow]=a4.y;
            As[buf][acol+2][arow]=a4.z; As[buf][acol+3][arow]=a4.w;
            *(float4*)&Bs[buf][brow][bcol] = b4;
            __syncthreads();
        }
    }
    #pragma unroll
    for(int i=0;i<8;i++){
        int r = row0 + ty*8 + i;
        if(r>=cnt) continue;
        int tok = g_elist[e*NTOK + r];
        float gv = g_egate[e*NTOK + r];
        #pragma unroll
        for(int j=0;j<8;j++){
            int c = col0 + tx*8 + j;
            float v = acc[i][j];
            if(s==0) v += b2[c];
            atomicAdd(&g_moe[(size_t)tok*DD + c], gv*v);
        }
    }
}

// ---------------- small SGEMM (router only, N=8) ----------------
__global__ __launch_bounds__(256) void k_sgemm(const float* __restrict__ A,
                                               const float* __restrict__ Bm,
                                               const float* __restrict__ bias,
                                               float* __restrict__ C,
                                               int M, int N, int Kd){
    __shared__ float As[16][64];
    __shared__ float Bs[16][64];
    int tx = threadIdx.x & 15, ty = threadIdx.x >> 4;
    int row0 = blockIdx.y*64, col0 = blockIdx.x*64;
    float acc[4][4] = {};
    for(int k0=0;k0<Kd;k0+=16){
        #pragma unroll
        for(int i=threadIdx.x;i<1024;i+=256){
            int m=i>>4, kk=i&15; int r=row0+m;
            As[kk][m] = (r<M)? A[(size_t)r*Kd + k0+kk] : 0.f;
        }
        #pragma unroll
        for(int i=threadIdx.x;i<1024;i+=256){
            int kk=i>>6, c=i&63; int cc=col0+c;
            Bs[kk][c] = (cc<N)? Bm[(size_t)(k0+kk)*N + cc] : 0.f;
        }
        __syncthreads();
        #pragma unroll
        for(int kk=0;kk<16;kk++){
            float4 a4 = *(const float4*)&As[kk][ty*4];
            float4 b4 = *(const float4*)&Bs[kk][tx*4];
            float a[4]={a4.x,a4.y,a4.z,a4.w};
            float b[4]={b4.x,b4.y,b4.z,b4.w};
            #pragma unroll
            for(int i=0;i<4;i++)
                #pragma unroll
                for(int j=0;j<4;j++)
                    acc[i][j] += a[i]*b[j];
        }
        __syncthreads();
    }
    #pragma unroll
    for(int i=0;i<4;i++){
        int r=row0+ty*4+i; if(r>=M) continue;
        #pragma unroll
        for(int j=0;j<4;j++){
            int c=col0+tx*4+j; if(c>=N) continue;
            C[(size_t)r*N + c] = acc[i][j] + bias[c];
        }
    }
}

// ---------------- lightning indexer scores ----------------
__global__ __launch_bounds__(256) void k_idxscore(const float* __restrict__ hw){
    int kt=blockIdx.x, qt=blockIdx.y, b=blockIdx.z;
    int tx=threadIdx.x&15, ty=threadIdx.x>>4;
    __shared__ float Qs[64][65];
    __shared__ float Ks[64][65];
    float acc[4][4] = {};
    for(int h=0;h<HHI;h++){
        for(int i=threadIdx.x;i<4096;i+=256){
            int r=i>>6, d=i&63;
            Qs[r][d] = g_qi[(size_t)(b*SSL + qt*64 + r)*(HHI*DII) + h*64 + d];
            Ks[r][d] = g_ki[(size_t)(b*SSL + kt*64 + r)*(HHI*DII) + h*64 + d];
        }
        __syncthreads();
        float w = hw[h];
        float dot[4][4] = {};
        #pragma unroll 16
        for(int d=0;d<64;d++){
            float a[4], bb[4];
            #pragma unroll
            for(int i=0;i<4;i++) a[i]=Qs[ty*4+i][d];
            #pragma unroll
            for(int j=0;j<4;j++) bb[j]=Ks[tx*4+j][d];
            #pragma unroll
            for(int i=0;i<4;i++)
                #pragma unroll
                for(int j=0;j<4;j++)
                    dot[i][j]+=a[i]*bb[j];
        }
        #pragma unroll
        for(int i=0;i<4;i++)
            #pragma unroll
            for(int j=0;j<4;j++)
                acc[i][j] += fmaxf(dot[i][j],0.f)*w;
        __syncthreads();
    }
    #pragma unroll
    for(int i=0;i<4;i++){
        int q = qt*64 + ty*4 + i;
        #pragma unroll
        for(int j=0;j<4;j++){
            int k = kt*64 + tx*4 + j;
            g_mask[((size_t)b*SSL + q)*SSL + k] = acc[i][j] + ((k<=q)?0.f:NEGV);
        }
    }
}

// ---------------- exact top-K threshold + final additive mask ----------------
__global__ __launch_bounds__(512) void k_topk(){
    int q=blockIdx.x, b=blockIdx.y, t=threadIdx.x;
    __shared__ float s[1024];
    size_t base = ((size_t)b*SSL + q)*SSL;
    s[t]     = g_mask[base+t];
    s[t+512] = g_mask[base+t+512];
    __syncthreads();
    for(int size=2;size<=1024;size<<=1){
        for(int stride=size>>1;stride>0;stride>>=1){
            int lo = 2*stride*(t/stride) + (t%stride);
            int hi = lo + stride;
            bool desc = ((lo & size)==0);
            float a=s[lo], bv=s[hi];
            if((a<bv)==desc){ s[lo]=bv; s[hi]=a; }
            __syncthreads();
        }
    }
    float thr = s[KTOP-1];
    for(int k=t;k<SSL;k+=512){
        float v = g_mask[base+k];
        g_mask[base+k] = (k<=q && v>=thr)? 0.f : NEGV;
    }
}

// ---------------- attention: 16 queries/block, fully-parallel online softmax ----------------
// grid (S/16, H, B), block 256; thread = (row = t>>4, cg = t&15)
__global__ __launch_bounds__(256) void k_attn(){
    int qt=blockIdx.x, h=blockIdx.y, b=blockIdx.z;
    int t=threadIdx.x;
    int row = t>>4;
    int cg  = t&15;
    __shared__ float qs[16][65];
    __shared__ float Ks[64][65];
    __shared__ float Vs[64][65];
    __shared__ float Sc[16][65];
    __shared__ float mrow[16], lrow[16];
    int q0 = qt*16;
    for(int i=t;i<16*64;i+=256){
        int r=i>>6, d=i&63;
        qs[r][d] = g_q[(size_t)(b*SSL + q0 + r)*DD + h*64 + d];
    }
    if(t<16){ mrow[t]=-1e30f; lrow[t]=0.f; }
    float oacc[4] = {0.f,0.f,0.f,0.f};
    __syncthreads();
    const float* maskrow = g_mask + ((size_t)b*SSL + (q0+row))*SSL;
    for(int k0=0;k0<SSL;k0+=64){
        for(int i=t;i<4096;i+=256){
            int r=i>>6, d=i&63;
            Ks[r][d] = g_k[(size_t)(b*SSL + k0 + r)*DD + h*64 + d];
            Vs[r][d] = g_v[(size_t)(b*SSL + k0 + r)*DD + h*64 + d];
        }
        __syncthreads();
        // QK: thread computes 4 score columns
        float sv[4];
        #pragma unroll
        for(int j=0;j<4;j++){
            int kc = cg*4 + j;
            float acc = 0.f;
            #pragma unroll 16
            for(int d=0;d<64;d++) acc += qs[row][d]*Ks[kc][d];
            sv[j] = acc*SCALE + maskrow[k0 + kc];
        }
        // online softmax, parallel over 16 lanes per row
        float mold = mrow[row];
        float lold = lrow[row];
        float tmax = fmaxf(fmaxf(sv[0],sv[1]), fmaxf(sv[2],sv[3]));
        tmax = fmaxf(tmax, mold);
        #pragma unroll
        for(int off=8;off>0;off>>=1)
            tmax = fmaxf(tmax, __shfl_xor_sync(0xffffffffu, tmax, off, 16));
        float c = __expf(mold - tmax);
        float lsum = 0.f;
        #pragma unroll
        for(int j=0;j<4;j++){
            float p = __expf(sv[j]-tmax);
            Sc[row][cg*4+j] = p;
            lsum += p;
        }
        #pragma unroll
        for(int off=8;off>0;off>>=1)
            lsum += __shfl_xor_sync(0xffffffffu, lsum, off, 16);
        if(cg==0){ mrow[row]=tmax; lrow[row]=lold*c + lsum; }
        __syncwarp();
        // PV: thread computes 4 output dims
        #pragma unroll
        for(int j=0;j<4;j++){
            int d = cg*4 + j;
            float a = oacc[j]*c;
            #pragma unroll 16
            for(int k=0;k<64;k++) a += Sc[row][k]*Vs[k][d];
            oacc[j] = a;
        }
        __syncthreads();
    }
    float linv = 1.0f/lrow[row];
    #pragma unroll
    for(int j=0;j<4;j++){
        int d = cg*4 + j;
        g_ao[(size_t)(b*SSL + q0 + row)*DD + h*64 + d] = oacc[j]*linv;
    }
}

// ---------------- router gating ----------------
__global__ void k_gate(){
    int n = blockIdx.x*blockDim.x + threadIdx.x;
    if(n>=NTOK) return;
    float p[EE]; float mx=-1e30f;
    for(int e=0;e<EE;e++){ p[e]=g_probs[n*EE+e]; mx=fmaxf(mx,p[e]); }
    for(int e=0;e<EE;e++) p[e]=__expf(p[e]-mx);
    int e1=0;
    for(int e=1;e<EE;e++) if(p[e]>p[e1]) e1=e;
    int e2=-1;
    for(int e=0;e<EE;e++) if(e!=e1 && (e2<0 || p[e]>p[e2])) e2=e;
    float den = p[e1]+p[e2];
    float w1 = p[e1]/den, w2 = p[e2]/den;
    int pos = atomicAdd(&g_ecount[e1],1);
    g_elist[e1*NTOK+pos]=n; g_egate[e1*NTOK+pos]=w1;
    pos = atomicAdd(&g_ecount[e2],1);
    g_elist[e2*NTOK+pos]=n; g_egate[e2*NTOK+pos]=w2;
}

// ================================ host ================================
extern "C" void kernel_launch(void* const* d_in, const int* in_sizes, int n_in,
                              void* d_out, int out_size){
    (void)in_sizes; (void)n_in; (void)out_size;
    const int*   ids  = (const int*)  d_in[0];
    const float* tok  = (const float*)d_in[1];
    const float* pos  = (const float*)d_in[2];
    const float* ln1g = (const float*)d_in[3];
    const float* ln1b = (const float*)d_in[4];
    const float* iqw  = (const float*)d_in[5];
    const float* iqb  = (const float*)d_in[6];
    const float* ikw  = (const float*)d_in[7];
    const float* ikb  = (const float*)d_in[8];
    const float* ihw  = (const float*)d_in[9];
    const float* wq   = (const float*)d_in[10];
    const float* bq   = (const float*)d_in[11];
    const float* wk   = (const float*)d_in[12];
    const float* bk   = (const float*)d_in[13];
    const float* wv   = (const float*)d_in[14];
    const float* bv   = (const float*)d_in[15];
    const float* wo   = (const float*)d_in[16];
    const float* bo   = (const float*)d_in[17];
    const float* ln2g = (const float*)d_in[18];
    const float* ln2b = (const float*)d_in[19];
    const float* rw   = (const float*)d_in[20];
    const float* rb   = (const float*)d_in[21];
    const float* ew1  = (const float*)d_in[22];
    const float* eb1  = (const float*)d_in[23];
    const float* ew2  = (const float*)d_in[24];
    const float* eb2  = (const float*)d_in[25];
    const float* lnfg = (const float*)d_in[26];
    const float* lnfb = (const float*)d_in[27];
    const float* ow   = (const float*)d_in[28];
    const float* ob   = (const float*)d_in[29];
    float* out = (float*)d_out;

    float *px,*ph,*pm,*pq,*pk,*pv,*pao,*pqi,*pki,*pprobs,*pmoe;
    int *pec;
    cudaGetSymbolAddress((void**)&px,  g_x);
    cudaGetSymbolAddress((void**)&ph,  g_h);
    cudaGetSymbolAddress((void**)&pm,  g_m);
    cudaGetSymbolAddress((void**)&pq,  g_q);
    cudaGetSymbolAddress((void**)&pk,  g_k);
    cudaGetSymbolAddress((void**)&pv,  g_v);
    cudaGetSymbolAddress((void**)&pao, g_ao);
    cudaGetSymbolAddress((void**)&pqi, g_qi);
    cudaGetSymbolAddress((void**)&pki, g_ki);
    cudaGetSymbolAddress((void**)&pprobs, g_probs);
    cudaGetSymbolAddress((void**)&pmoe, g_moe);
    cudaGetSymbolAddress((void**)&pec, g_ecount);

    k_embed<<<NTOK,512>>>(ids, tok, pos);

    for(int l=0;l<LLN;l++){
        // --- attention block ---
        k_ln<<<NTOK,256>>>(px, ln1g + l*DD, ln1b + l*DD, ph);
        {   // indexer q/k projections, batched (N=256)
            B3 p;
            p.B0 = iqw + (size_t)l*DD*HHI*DII; p.c0 = iqb + l*HHI*DII; p.C0 = pqi;
            p.B1 = ikw + (size_t)l*DD*HHI*DII; p.c1 = ikb + l*HHI*DII; p.C1 = pki;
            p.B2 = p.B0; p.c2 = p.c0; p.C2 = pqi;
            k_gemm128b3<<<dim3(2,16,2),256>>>(ph, p, HHI*DII, DD);
        }
        k_idxscore<<<dim3(SSL/64, SSL/64, BB),256>>>(ihw + l*HHI);
        k_topk<<<dim3(SSL, BB),512>>>();
        {   // QKV batched (N=512)
            B3 p;
            p.B0 = wq + (size_t)l*DD*DD; p.c0 = bq + l*DD; p.C0 = pq;
            p.B1 = wk + (size_t)l*DD*DD; p.c1 = bk + l*DD; p.C1 = pk;
            p.B2 = wv + (size_t)l*DD*DD; p.c2 = bv + l*DD; p.C2 = pv;
            k_gemm128b3<<<dim3(4,16,3),256>>>(ph, p, DD, DD);
        }
        k_attn<<<dim3(SSL/16, HHN, BB),256>>>();
        // x = x + ao @ wo + bo
        k_gemm128<<<dim3(4,16),256>>>(pao, wo + (size_t)l*DD*DD, bo + l*DD, px, px, DD, DD);

        // --- MoE block ---
        k_ln<<<NTOK,256>>>(px, ln2g + l*DD, ln2b + l*DD, pm);
        k_sgemm<<<dim3(1,32),256>>>(pm, rw + (size_t)l*DD*EE, rb + l*EE, pprobs, NTOK, EE, DD);
        k_zeroi<<<1,32>>>(pec, EE);
        k_gate<<<NTOK/256,256>>>();
        k_zerof<<<(NTOK*DD)/256,256>>>(pmoe, NTOK*DD);
        k_moe1<<<dim3(FFD/128, NTOK/128, EE),256>>>(ew1 + (size_t)l*EE*DD*FFD, eb1 + (size_t)l*EE*FFD);
        k_moe2<<<dim3(DD/128, NTOK/128, EE*2),256>>>(ew2 + (size_t)l*EE*FFD*DD, eb2 + (size_t)l*EE*DD);
        k_add<<<(NTOK*DD)/256,256>>>(px, pmoe, NTOK*DD);
    }

    // --- final LN + vocab projection ---
    k_ln<<<NTOK,256>>>(px, lnfg, lnfb, ph);
    k_gemm128<<<dim3(VV/128, NTOK/128),256>>>(ph, ow, ob, nullptr, out, VV, DD);
}